// round 16
// baseline (speedup 1.0000x reference)
#include <cuda_runtime.h>
#include <math.h>
#include <stdint.h>

#define B_ 2
#define T_ 2048
#define E_ 1024
#define H_ 16
#define D_ 64
#define M_ (B_*T_)
#define N_ 1024
#define K_ 1024

// Scratch (allocation-free rule: __device__ globals)
__device__ float g_q[M_*N_];
__device__ float g_k[M_*N_];
__device__ float g_v[M_*N_];
__device__ float g_z[M_*N_];
__device__ float g_wt[4ull * 1024 * 1024];   // K-major transposed weights
__device__ int   g_mask_is_byte;

// ---------------------------------------------------------------------------
// Helpers
// ---------------------------------------------------------------------------
__device__ __forceinline__ unsigned f2tf(float x) {
    unsigned u;
    asm("cvt.rna.tf32.f32 %0, %1;" : "=r"(u) : "f"(x));
    return u;
}

__device__ __forceinline__ void mma_tf32(float c[4],
    unsigned a0, unsigned a1, unsigned a2, unsigned a3,
    unsigned b0, unsigned b1)
{
    asm volatile(
        "mma.sync.aligned.m16n8k8.row.col.f32.tf32.tf32.f32 "
        "{%0,%1,%2,%3}, {%4,%5,%6,%7}, {%8,%9}, {%0,%1,%2,%3};\n"
        : "+f"(c[0]), "+f"(c[1]), "+f"(c[2]), "+f"(c[3])
        : "r"(a0), "r"(a1), "r"(a2), "r"(a3), "r"(b0), "r"(b1));
}

// k-permutation within an 8-group: order [0,4,1,5,2,6,3,7] so that
// (k=t, k=t+4) land at adjacent positions (2t, 2t+1) -> LDS.64 frag loads.
__device__ __forceinline__ int pos8(int c) {
    return (c & 4) ? (((c & 3) << 1) | 1) : (c << 1);
}

// ---------------------------------------------------------------------------
// Mask dtype detection (1-byte vs 4-byte bool storage)
// ---------------------------------------------------------------------------
__global__ void detect_mask_kernel(const unsigned int* __restrict__ w) {
    __shared__ int bad;
    if (threadIdx.x == 0) bad = 0;
    __syncthreads();
    int local = 0;
    for (int i = threadIdx.x; i < 4096; i += blockDim.x) {
        unsigned int x = w[i];
        if (x != 0u && x != 1u && x != 0x3F800000u) local = 1;
    }
    if (local) atomicOr(&bad, 1);
    __syncthreads();
    if (threadIdx.x == 0) g_mask_is_byte = bad;
}

// ---------------------------------------------------------------------------
// Batched 1024x1024 transpose: out[z][n][k] = W_z[k][n]  (4 weight matrices)
// ---------------------------------------------------------------------------
__global__ void transpose4(const float* __restrict__ w0, const float* __restrict__ w1,
                           const float* __restrict__ w2, const float* __restrict__ w3,
                           float* __restrict__ out)
{
    __shared__ float t[32][33];
    const float* src = (blockIdx.z == 0) ? w0 : (blockIdx.z == 1) ? w1
                     : (blockIdx.z == 2) ? w2 : w3;
    float* dst = out + (size_t)blockIdx.z * 1024 * 1024;
    int x = blockIdx.x * 32 + threadIdx.x;
    int y = blockIdx.y * 32 + threadIdx.y;
    #pragma unroll
    for (int j = 0; j < 32; j += 8)
        t[threadIdx.y + j][threadIdx.x] = src[(size_t)(y + j) * 1024 + x];
    __syncthreads();
    x = blockIdx.y * 32 + threadIdx.x;
    y = blockIdx.x * 32 + threadIdx.y;
    #pragma unroll
    for (int j = 0; j < 32; j += 8)
        dst[(size_t)(y + j) * 1024 + x] = t[threadIdx.x][threadIdx.y + j];
}

// ---------------------------------------------------------------------------
// TF32 mma.sync GEMM body: C[M,N] = A[M,K] @ BT^T + bias (BT K-major [N,K]).
// 128x128 tile, BK=16, double-buffered smem (1 bar/chunk), k-permuted layout
// with pitch 24 (== 8 mod 32 -> conflict-free LDS.64 fragment loads).
// ---------------------------------------------------------------------------
#define GP 24               // smem pitch in words (16 data + 8 pad)
#define GBUF (128 * GP)     // words per buffer per matrix

__device__ __forceinline__ void gemm_body(
    const float* __restrict__ A, const float* __restrict__ BT,
    const float* __restrict__ bias, float* __restrict__ C,
    unsigned* __restrict__ As, unsigned* __restrict__ Bs)
{
    const int tid = threadIdx.x, wid = tid >> 5, lane = tid & 31;
    const int g = lane >> 2, t = lane & 3;
    const int wm = wid & 1, wn = wid >> 1;           // warp grid 2 x 4
    const int m0 = blockIdx.y << 7, n0 = blockIdx.x << 7;

    const int r0 = tid >> 2;                         // load row 0..63 (+64)
    const int kq = (tid & 3) << 2;                   // k-offset 0,4,8,12
    const int pb = ((kq >> 3) << 3) | ((kq & 4) >> 2);  // perm base (+2*i)

    const float* Ap0 = A  + (size_t)(m0 + r0) * K_ + kq;
    const float* Ap1 = Ap0 + (size_t)64 * K_;
    const float* Bp0 = BT + (size_t)(n0 + r0) * K_ + kq;
    const float* Bp1 = Bp0 + (size_t)64 * K_;

    float acc[4][4][4];
    #pragma unroll
    for (int mi = 0; mi < 4; mi++)
        #pragma unroll
        for (int ni = 0; ni < 4; ni++)
            #pragma unroll
            for (int r = 0; r < 4; r++) acc[mi][ni][r] = 0.f;

    float4 av0 = *(const float4*)Ap0, av1 = *(const float4*)Ap1;
    float4 bv0 = *(const float4*)Bp0, bv1 = *(const float4*)Bp1;

    for (int c = 0; c < 64; ++c) {
        unsigned* ab = As + (c & 1) * GBUF;
        unsigned* bb = Bs + (c & 1) * GBUF;
        unsigned* p;
        p = ab + r0 * GP + pb;
        p[0] = f2tf(av0.x); p[2] = f2tf(av0.y); p[4] = f2tf(av0.z); p[6] = f2tf(av0.w);
        p = ab + (r0 + 64) * GP + pb;
        p[0] = f2tf(av1.x); p[2] = f2tf(av1.y); p[4] = f2tf(av1.z); p[6] = f2tf(av1.w);
        p = bb + r0 * GP + pb;
        p[0] = f2tf(bv0.x); p[2] = f2tf(bv0.y); p[4] = f2tf(bv0.z); p[6] = f2tf(bv0.w);
        p = bb + (r0 + 64) * GP + pb;
        p[0] = f2tf(bv1.x); p[2] = f2tf(bv1.y); p[4] = f2tf(bv1.z); p[6] = f2tf(bv1.w);
        __syncthreads();

        if (c < 63) {   // prefetch next chunk while computing this one
            int k0 = (c + 1) << 4;
            av0 = *(const float4*)(Ap0 + k0); av1 = *(const float4*)(Ap1 + k0);
            bv0 = *(const float4*)(Bp0 + k0); bv1 = *(const float4*)(Bp1 + k0);
        }

        #pragma unroll
        for (int kk = 0; kk < 16; kk += 8) {
            uint2 alo[4], ahi[4], bfr[4];
            #pragma unroll
            for (int mi = 0; mi < 4; mi++) {
                int row = wm * 64 + mi * 16 + g;
                alo[mi] = *(const uint2*)(ab + row * GP + kk + 2 * t);
                ahi[mi] = *(const uint2*)(ab + (row + 8) * GP + kk + 2 * t);
            }
            #pragma unroll
            for (int ni = 0; ni < 4; ni++) {
                int col = wn * 32 + ni * 8 + g;
                bfr[ni] = *(const uint2*)(bb + col * GP + kk + 2 * t);
            }
            #pragma unroll
            for (int mi = 0; mi < 4; mi++)
                #pragma unroll
                for (int ni = 0; ni < 4; ni++)
                    mma_tf32(acc[mi][ni], alo[mi].x, ahi[mi].x, alo[mi].y,
                             ahi[mi].y, bfr[ni].x, bfr[ni].y);
        }
    }

    #pragma unroll
    for (int mi = 0; mi < 4; mi++) {
        #pragma unroll
        for (int ni = 0; ni < 4; ni++) {
            int row = m0 + wm * 64 + mi * 16 + g;
            int col = n0 + wn * 32 + ni * 8 + 2 * t;
            float bz0 = bias[col], bz1 = bias[col + 1];
            float2 w0 = make_float2(acc[mi][ni][0] + bz0, acc[mi][ni][1] + bz1);
            float2 w1 = make_float2(acc[mi][ni][2] + bz0, acc[mi][ni][3] + bz1);
            *(float2*)(C + (size_t)row * N_ + col) = w0;
            *(float2*)(C + (size_t)(row + 8) * N_ + col) = w1;
        }
    }
}

#define GEMM_SMEM (4 * GBUF * 4)   // 2 buffers x (A+B) x 4B = 49152 B

__global__ __launch_bounds__(256, 2) void gemm_qkv(
    const float* __restrict__ A, const float* __restrict__ WT,
    const float* __restrict__ bq, const float* __restrict__ bk,
    const float* __restrict__ bv,
    float* __restrict__ q, float* __restrict__ k, float* __restrict__ v)
{
    extern __shared__ unsigned gsm[];
    const int z = blockIdx.z;
    const float* BT = WT + (size_t)z * 1024 * 1024;
    const float* bias = (z == 0) ? bq : (z == 1) ? bk : bv;
    float* C = (z == 0) ? q : (z == 1) ? k : v;
    gemm_body(A, BT, bias, C, gsm, gsm + 2 * GBUF);
}

__global__ __launch_bounds__(256, 2) void gemm_one(
    const float* __restrict__ A, const float* __restrict__ BT,
    const float* __restrict__ bias, float* __restrict__ C)
{
    extern __shared__ unsigned gsm[];
    gemm_body(A, BT, bias, C, gsm, gsm + 2 * GBUF);
}

// ---------------------------------------------------------------------------
// TF32 mma.sync flash attention, 128 threads / 4 warps, 32 q-rows per warp
// (mi=2): K/V fragments feed TWO row-tiles each -> half the L1 frag traffic.
// P never touches smem: S C-fragments are re-laid into PV A-fragments with
// warp shuffles. Grid (T/128, H, B). BQ=128, BC=64, 3 CTAs/SM target.
// Qs/Ks: pitch 72 (== 8 mod 32), k-permuted. Vs: grouped-permuted [8][64][8].
// ---------------------------------------------------------------------------
#define FP 72

__global__ __launch_bounds__(128, 3) void flash_attn_tc(const void* __restrict__ maskp)
{
    extern __shared__ unsigned smu[];
    unsigned* Qs = smu;                   // [128][FP] permuted d
    unsigned* Ks = Qs + 128 * FP;         // [64][FP]  permuted d
    unsigned* Vs = Ks + 64 * FP;          // [8][64][8] grouped-permuted

    const int b = blockIdx.z, h = blockIdx.y, qt = blockIdx.x;
    const int tid = threadIdx.x;
    const int wid = tid >> 5, lane = tid & 31;
    const int g = lane >> 2, t = lane & 3;
    const int qrow = wid * 32;            // 4 warps x 32 q-rows
    const int src1 = (lane & 28) | (t >> 1);   // shuffle src: col t
    const int src2 = src1 + 2;                 // shuffle src: col t+4
    const bool todd = (t & 1);

    const int is_byte = g_mask_is_byte;
    const unsigned char* mask_b = (const unsigned char*)maskp;
    const int*           mask_w = (const int*)maskp;

    // Load Q tile (128 x 64), scale folded, permuted store
    #pragma unroll
    for (int e = 0; e < 16; e++) {
        int idx = tid + e * 128;
        int r = idx >> 4, d4 = (idx & 15) << 2;
        int pbq = ((d4 >> 3) << 3) | ((d4 & 4) >> 2);
        float4 qv = *(const float4*)(g_q + (size_t)(b * T_ + qt * 128 + r) * N_ + h * D_ + d4);
        unsigned* p = Qs + r * FP + pbq;
        p[0] = f2tf(qv.x * 0.125f); p[2] = f2tf(qv.y * 0.125f);
        p[4] = f2tf(qv.z * 0.125f); p[6] = f2tf(qv.w * 0.125f);
    }

    float m_i[4], l_i[4];           // [mi*2 + half]
    #pragma unroll
    for (int i = 0; i < 4; i++) { m_i[i] = -INFINITY; l_i[i] = 0.f; }
    float o[2][8][4];
    #pragma unroll
    for (int mi = 0; mi < 2; mi++)
        #pragma unroll
        for (int nt = 0; nt < 8; nt++)
            #pragma unroll
            for (int r = 0; r < 4; r++) o[mi][nt][r] = 0.f;

    for (int kt = 0; kt < T_ / 64; kt++) {
        __syncthreads();
        // K tile (64 x 64), row-major permuted-d
        #pragma unroll
        for (int e = 0; e < 8; e++) {
            int idx = tid + e * 128;
            int r = idx >> 4, d4 = (idx & 15) << 2;
            int pbk = ((d4 >> 3) << 3) | ((d4 & 4) >> 2);
            size_t base = (size_t)(b * T_ + kt * 64 + r) * N_ + h * D_ + d4;
            float4 kv = *(const float4*)(g_k + base);
            unsigned* p = Ks + r * FP + pbk;
            p[0] = f2tf(kv.x); p[2] = f2tf(kv.y); p[4] = f2tf(kv.z); p[6] = f2tf(kv.w);
        }
        // V tile: grouped-permuted
        #pragma unroll
        for (int e = 0; e < 4; e++) {
            int idx = tid + e * 128;        // 0..511
            int g8 = idx >> 6;              // k-group 0..7
            int n  = idx & 63;
            const float* vp = g_v + (size_t)(b * T_ + kt * 64 + g8 * 8) * N_ + h * D_ + n;
            unsigned vr[8];
            #pragma unroll
            for (int kr = 0; kr < 8; kr++)
                vr[pos8(kr)] = f2tf(vp[(size_t)kr * N_]);
            unsigned* vdst = Vs + g8 * 512 + n * 8;
            *(uint4*)(vdst + 0) = make_uint4(vr[0], vr[1], vr[2], vr[3]);
            *(uint4*)(vdst + 4) = make_uint4(vr[4], vr[5], vr[6], vr[7]);
        }
        __syncthreads();

        // ---- S = Q @ K^T  (warp: 32 x 64; K-frag shared across both mi) ----
        float s[2][8][4];
        #pragma unroll
        for (int mi = 0; mi < 2; mi++)
            #pragma unroll
            for (int nt = 0; nt < 8; nt++)
                #pragma unroll
                for (int r = 0; r < 4; r++) s[mi][nt][r] = 0.f;

        #pragma unroll
        for (int kk = 0; kk < 8; kk++) {
            uint2 qlo[2], qhi[2];
            #pragma unroll
            for (int mi = 0; mi < 2; mi++) {
                qlo[mi] = *(const uint2*)(Qs + (qrow + mi * 16 + g) * FP + kk * 8 + 2 * t);
                qhi[mi] = *(const uint2*)(Qs + (qrow + mi * 16 + g + 8) * FP + kk * 8 + 2 * t);
            }
            #pragma unroll
            for (int nt = 0; nt < 8; nt++) {
                uint2 kb = *(const uint2*)(Ks + (nt * 8 + g) * FP + kk * 8 + 2 * t);
                mma_tf32(s[0][nt], qlo[0].x, qhi[0].x, qlo[0].y, qhi[0].y, kb.x, kb.y);
                mma_tf32(s[1][nt], qlo[1].x, qhi[1].x, qlo[1].y, qhi[1].y, kb.x, kb.y);
            }
        }

        // ---- mask + online softmax (fp32) ----
        #pragma unroll
        for (int mi = 0; mi < 2; mi++) {
            #pragma unroll
            for (int half = 0; half < 2; half++) {
                const int r0 = half * 2;
                const int li = mi * 2 + half;
                int rowg = qt * 128 + qrow + mi * 16 + half * 8 + g;
                size_t mbase = ((size_t)b * T_ + rowg) * T_ + kt * 64;

                #pragma unroll
                for (int nt = 0; nt < 8; nt++) {
                    int col = nt * 8 + 2 * t;
                    int mv0, mv1;
                    if (is_byte) {
                        uchar2 u = *(const uchar2*)(mask_b + mbase + col);
                        mv0 = u.x; mv1 = u.y;
                    } else {
                        int2 u = *(const int2*)(mask_w + mbase + col);
                        mv0 = u.x; mv1 = u.y;
                    }
                    if (mv0 == 0) s[mi][nt][r0 + 0] = -3.402823466e38f;
                    if (mv1 == 0) s[mi][nt][r0 + 1] = -3.402823466e38f;
                }

                float mx = -INFINITY;
                #pragma unroll
                for (int nt = 0; nt < 8; nt++)
                    mx = fmaxf(mx, fmaxf(s[mi][nt][r0], s[mi][nt][r0 + 1]));
                mx = fmaxf(mx, __shfl_xor_sync(0xffffffffu, mx, 1));
                mx = fmaxf(mx, __shfl_xor_sync(0xffffffffu, mx, 2));

                float mnew = fmaxf(m_i[li], mx);
                float corr = __expf(m_i[li] - mnew);
                float rs = 0.f;
                #pragma unroll
                for (int nt = 0; nt < 8; nt++) {
                    float p0 = __expf(s[mi][nt][r0] - mnew);
                    float p1 = __expf(s[mi][nt][r0 + 1] - mnew);
                    rs += p0 + p1;
                    // convert to tf32 bits in-place (P operand for PV mma)
                    s[mi][nt][r0]     = __uint_as_float(f2tf(p0));
                    s[mi][nt][r0 + 1] = __uint_as_float(f2tf(p1));
                }
                rs += __shfl_xor_sync(0xffffffffu, rs, 1);
                rs += __shfl_xor_sync(0xffffffffu, rs, 2);
                l_i[li] = l_i[li] * corr + rs;
                m_i[li] = mnew;
                #pragma unroll
                for (int nt = 0; nt < 8; nt++) {
                    o[mi][nt][r0] *= corr; o[mi][nt][r0 + 1] *= corr;
                }
            }
        }

        // ---- O += P @ V : P A-frags built by shuffle from S C-frags ----
        #pragma unroll
        for (int kk = 0; kk < 8; kk++) {
            unsigned pa[2][4];
            #pragma unroll
            for (int mi = 0; mi < 2; mi++) {
                float x0 = __shfl_sync(0xffffffffu, s[mi][kk][0], src1);
                float x1 = __shfl_sync(0xffffffffu, s[mi][kk][1], src1);
                float x2 = __shfl_sync(0xffffffffu, s[mi][kk][0], src2);
                float x3 = __shfl_sync(0xffffffffu, s[mi][kk][1], src2);
                float y0 = __shfl_sync(0xffffffffu, s[mi][kk][2], src1);
                float y1 = __shfl_sync(0xffffffffu, s[mi][kk][3], src1);
                float y2 = __shfl_sync(0xffffffffu, s[mi][kk][2], src2);
                float y3 = __shfl_sync(0xffffffffu, s[mi][kk][3], src2);
                pa[mi][0] = __float_as_uint(todd ? x1 : x0);   // P[g][t]
                pa[mi][1] = __float_as_uint(todd ? y1 : y0);   // P[g+8][t]
                pa[mi][2] = __float_as_uint(todd ? x3 : x2);   // P[g][t+4]
                pa[mi][3] = __float_as_uint(todd ? y3 : y2);   // P[g+8][t+4]
            }
            const unsigned* vg = Vs + kk * 512;
            #pragma unroll
            for (int nt = 0; nt < 8; nt++) {
                uint2 vb = *(const uint2*)(vg + (nt * 8 + g) * 8 + 2 * t);
                mma_tf32(o[0][nt], pa[0][0], pa[0][1], pa[0][2], pa[0][3], vb.x, vb.y);
                mma_tf32(o[1][nt], pa[1][0], pa[1][1], pa[1][2], pa[1][3], vb.x, vb.y);
            }
        }
    }

    // Epilogue: normalize, write z[b,t,h,d]
    #pragma unroll
    for (int mi = 0; mi < 2; mi++) {
        #pragma unroll
        for (int half = 0; half < 2; half++) {
            float inv = 1.f / l_i[mi * 2 + half];
            int rowg = qt * 128 + qrow + mi * 16 + half * 8 + g;
            #pragma unroll
            for (int nt = 0; nt < 8; nt++) {
                float2 ov = make_float2(o[mi][nt][half * 2] * inv,
                                        o[mi][nt][half * 2 + 1] * inv);
                *(float2*)(g_z + (size_t)(b * T_ + rowg) * N_ + h * D_ + nt * 8 + 2 * t) = ov;
            }
        }
    }
}

#define ATTN_SMEM ((128 * FP + 64 * FP + 4096) * 4)   // 71680 B = 70 KB

// ---------------------------------------------------------------------------
extern "C" void kernel_launch(void* const* d_in, const int* in_sizes, int n_in,
                              void* d_out, int out_size)
{
    const float* embed = (const float*)d_in[0];
    const void*  mask  = d_in[1];
    const float* Wq = (const float*)d_in[2]; const float* bq = (const float*)d_in[3];
    const float* Wk = (const float*)d_in[4]; const float* bk = (const float*)d_in[5];
    const float* Wv = (const float*)d_in[6]; const float* bv = (const float*)d_in[7];
    const float* Wz = (const float*)d_in[8]; const float* bz = (const float*)d_in[9];
    float* out = (float*)d_out;

    float *q, *k, *v, *z, *wt;
    cudaGetSymbolAddress((void**)&q, g_q);
    cudaGetSymbolAddress((void**)&k, g_k);
    cudaGetSymbolAddress((void**)&v, g_v);
    cudaGetSymbolAddress((void**)&z, g_z);
    cudaGetSymbolAddress((void**)&wt, g_wt);

    detect_mask_kernel<<<1, 256>>>((const unsigned int*)mask);
    transpose4<<<dim3(32, 32, 4), dim3(32, 8)>>>(Wq, Wk, Wv, Wz, wt);

    cudaFuncSetAttribute(gemm_qkv, cudaFuncAttributeMaxDynamicSharedMemorySize,
                         GEMM_SMEM);
    cudaFuncSetAttribute(gemm_one, cudaFuncAttributeMaxDynamicSharedMemorySize,
                         GEMM_SMEM);
    gemm_qkv<<<dim3(N_ / 128, M_ / 128, 3), 256, GEMM_SMEM>>>(
        embed, wt, bq, bk, bv, q, k, v);

    cudaFuncSetAttribute(flash_attn_tc,
                         cudaFuncAttributeMaxDynamicSharedMemorySize, ATTN_SMEM);
    flash_attn_tc<<<dim3(T_ / 128, H_, B_), 128, ATTN_SMEM>>>(mask);

    gemm_one<<<dim3(N_ / 128, M_ / 128), 256, GEMM_SMEM>>>(
        z, wt + 3ull * 1024 * 1024, bz, out);
}

// round 17
// speedup vs baseline: 1.7128x; 1.7128x over previous
#include <cuda_runtime.h>
#include <math.h>
#include <stdint.h>

#define B_ 2
#define T_ 2048
#define E_ 1024
#define H_ 16
#define D_ 64
#define M_ (B_*T_)
#define N_ 1024
#define K_ 1024

// Scratch (allocation-free rule: __device__ globals)
__device__ float g_q[M_*N_];
__device__ float g_k[M_*N_];
__device__ float g_v[M_*N_];
__device__ float g_z[M_*N_];
__device__ float g_wt[4ull * 1024 * 1024];   // K-major transposed weights
__device__ int   g_mask_is_byte;

// ---------------------------------------------------------------------------
// Helpers
// ---------------------------------------------------------------------------
__device__ __forceinline__ unsigned f2tf(float x) {
    unsigned u;
    asm("cvt.rna.tf32.f32 %0, %1;" : "=r"(u) : "f"(x));
    return u;
}

__device__ __forceinline__ void mma_tf32(float c[4],
    unsigned a0, unsigned a1, unsigned a2, unsigned a3,
    unsigned b0, unsigned b1)
{
    asm volatile(
        "mma.sync.aligned.m16n8k8.row.col.f32.tf32.tf32.f32 "
        "{%0,%1,%2,%3}, {%4,%5,%6,%7}, {%8,%9}, {%0,%1,%2,%3};\n"
        : "+f"(c[0]), "+f"(c[1]), "+f"(c[2]), "+f"(c[3])
        : "r"(a0), "r"(a1), "r"(a2), "r"(a3), "r"(b0), "r"(b1));
}

// k-permutation within an 8-group: order [0,4,1,5,2,6,3,7] so that
// (k=t, k=t+4) land at adjacent positions (2t, 2t+1) -> LDS.64 frag loads.
__device__ __forceinline__ int pos8(int c) {
    return (c & 4) ? (((c & 3) << 1) | 1) : (c << 1);
}

// ---------------------------------------------------------------------------
// Mask dtype detection (1-byte vs 4-byte bool storage)
// ---------------------------------------------------------------------------
__global__ void detect_mask_kernel(const unsigned int* __restrict__ w) {
    __shared__ int bad;
    if (threadIdx.x == 0) bad = 0;
    __syncthreads();
    int local = 0;
    for (int i = threadIdx.x; i < 4096; i += blockDim.x) {
        unsigned int x = w[i];
        if (x != 0u && x != 1u && x != 0x3F800000u) local = 1;
    }
    if (local) atomicOr(&bad, 1);
    __syncthreads();
    if (threadIdx.x == 0) g_mask_is_byte = bad;
}

// ---------------------------------------------------------------------------
// Batched 1024x1024 transpose: out[z][n][k] = W_z[k][n]  (4 weight matrices)
// ---------------------------------------------------------------------------
__global__ void transpose4(const float* __restrict__ w0, const float* __restrict__ w1,
                           const float* __restrict__ w2, const float* __restrict__ w3,
                           float* __restrict__ out)
{
    __shared__ float t[32][33];
    const float* src = (blockIdx.z == 0) ? w0 : (blockIdx.z == 1) ? w1
                     : (blockIdx.z == 2) ? w2 : w3;
    float* dst = out + (size_t)blockIdx.z * 1024 * 1024;
    int x = blockIdx.x * 32 + threadIdx.x;
    int y = blockIdx.y * 32 + threadIdx.y;
    #pragma unroll
    for (int j = 0; j < 32; j += 8)
        t[threadIdx.y + j][threadIdx.x] = src[(size_t)(y + j) * 1024 + x];
    __syncthreads();
    x = blockIdx.y * 32 + threadIdx.x;
    y = blockIdx.x * 32 + threadIdx.y;
    #pragma unroll
    for (int j = 0; j < 32; j += 8)
        dst[(size_t)(y + j) * 1024 + x] = t[threadIdx.x][threadIdx.y + j];
}

// ---------------------------------------------------------------------------
// TF32 mma.sync GEMM body: C[M,N] = A[M,K] @ BT^T + bias (BT K-major [N,K]).
// 128x128 tile, BK=16, double-buffered smem (1 bar/chunk), k-permuted layout
// with pitch 24 (== 8 mod 32 -> conflict-free LDS.64 fragment loads).
// ---------------------------------------------------------------------------
#define GP 24               // smem pitch in words (16 data + 8 pad)
#define GBUF (128 * GP)     // words per buffer per matrix

__device__ __forceinline__ void gemm_body(
    const float* __restrict__ A, const float* __restrict__ BT,
    const float* __restrict__ bias, float* __restrict__ C,
    unsigned* __restrict__ As, unsigned* __restrict__ Bs)
{
    const int tid = threadIdx.x, wid = tid >> 5, lane = tid & 31;
    const int g = lane >> 2, t = lane & 3;
    const int wm = wid & 1, wn = wid >> 1;           // warp grid 2 x 4
    const int m0 = blockIdx.y << 7, n0 = blockIdx.x << 7;

    const int r0 = tid >> 2;                         // load row 0..63 (+64)
    const int kq = (tid & 3) << 2;                   // k-offset 0,4,8,12
    const int pb = ((kq >> 3) << 3) | ((kq & 4) >> 2);  // perm base (+2*i)

    const float* Ap0 = A  + (size_t)(m0 + r0) * K_ + kq;
    const float* Ap1 = Ap0 + (size_t)64 * K_;
    const float* Bp0 = BT + (size_t)(n0 + r0) * K_ + kq;
    const float* Bp1 = Bp0 + (size_t)64 * K_;

    float acc[4][4][4];
    #pragma unroll
    for (int mi = 0; mi < 4; mi++)
        #pragma unroll
        for (int ni = 0; ni < 4; ni++)
            #pragma unroll
            for (int r = 0; r < 4; r++) acc[mi][ni][r] = 0.f;

    float4 av0 = *(const float4*)Ap0, av1 = *(const float4*)Ap1;
    float4 bv0 = *(const float4*)Bp0, bv1 = *(const float4*)Bp1;

    for (int c = 0; c < 64; ++c) {
        unsigned* ab = As + (c & 1) * GBUF;
        unsigned* bb = Bs + (c & 1) * GBUF;
        unsigned* p;
        p = ab + r0 * GP + pb;
        p[0] = f2tf(av0.x); p[2] = f2tf(av0.y); p[4] = f2tf(av0.z); p[6] = f2tf(av0.w);
        p = ab + (r0 + 64) * GP + pb;
        p[0] = f2tf(av1.x); p[2] = f2tf(av1.y); p[4] = f2tf(av1.z); p[6] = f2tf(av1.w);
        p = bb + r0 * GP + pb;
        p[0] = f2tf(bv0.x); p[2] = f2tf(bv0.y); p[4] = f2tf(bv0.z); p[6] = f2tf(bv0.w);
        p = bb + (r0 + 64) * GP + pb;
        p[0] = f2tf(bv1.x); p[2] = f2tf(bv1.y); p[4] = f2tf(bv1.z); p[6] = f2tf(bv1.w);
        __syncthreads();

        if (c < 63) {   // prefetch next chunk while computing this one
            int k0 = (c + 1) << 4;
            av0 = *(const float4*)(Ap0 + k0); av1 = *(const float4*)(Ap1 + k0);
            bv0 = *(const float4*)(Bp0 + k0); bv1 = *(const float4*)(Bp1 + k0);
        }

        #pragma unroll
        for (int kk = 0; kk < 16; kk += 8) {
            uint2 alo[4], ahi[4], bfr[4];
            #pragma unroll
            for (int mi = 0; mi < 4; mi++) {
                int row = wm * 64 + mi * 16 + g;
                alo[mi] = *(const uint2*)(ab + row * GP + kk + 2 * t);
                ahi[mi] = *(const uint2*)(ab + (row + 8) * GP + kk + 2 * t);
            }
            #pragma unroll
            for (int ni = 0; ni < 4; ni++) {
                int col = wn * 32 + ni * 8 + g;
                bfr[ni] = *(const uint2*)(bb + col * GP + kk + 2 * t);
            }
            #pragma unroll
            for (int mi = 0; mi < 4; mi++)
                #pragma unroll
                for (int ni = 0; ni < 4; ni++)
                    mma_tf32(acc[mi][ni], alo[mi].x, ahi[mi].x, alo[mi].y,
                             ahi[mi].y, bfr[ni].x, bfr[ni].y);
        }
    }

    #pragma unroll
    for (int mi = 0; mi < 4; mi++) {
        #pragma unroll
        for (int ni = 0; ni < 4; ni++) {
            int row = m0 + wm * 64 + mi * 16 + g;
            int col = n0 + wn * 32 + ni * 8 + 2 * t;
            float bz0 = bias[col], bz1 = bias[col + 1];
            float2 w0 = make_float2(acc[mi][ni][0] + bz0, acc[mi][ni][1] + bz1);
            float2 w1 = make_float2(acc[mi][ni][2] + bz0, acc[mi][ni][3] + bz1);
            *(float2*)(C + (size_t)row * N_ + col) = w0;
            *(float2*)(C + (size_t)(row + 8) * N_ + col) = w1;
        }
    }
}

#define GEMM_SMEM (4 * GBUF * 4)   // 2 buffers x (A+B) x 4B = 49152 B

__global__ __launch_bounds__(256, 2) void gemm_qkv(
    const float* __restrict__ A, const float* __restrict__ WT,
    const float* __restrict__ bq, const float* __restrict__ bk,
    const float* __restrict__ bv,
    float* __restrict__ q, float* __restrict__ k, float* __restrict__ v)
{
    extern __shared__ unsigned gsm[];
    const int z = blockIdx.z;
    const float* BT = WT + (size_t)z * 1024 * 1024;
    const float* bias = (z == 0) ? bq : (z == 1) ? bk : bv;
    float* C = (z == 0) ? q : (z == 1) ? k : v;
    gemm_body(A, BT, bias, C, gsm, gsm + 2 * GBUF);
}

__global__ __launch_bounds__(256, 2) void gemm_one(
    const float* __restrict__ A, const float* __restrict__ BT,
    const float* __restrict__ bias, float* __restrict__ C)
{
    extern __shared__ unsigned gsm[];
    gemm_body(A, BT, bias, C, gsm, gsm + 2 * GBUF);
}

// ---------------------------------------------------------------------------
// TF32 mma.sync flash attention. 256 threads / 8 warps, 16 q-rows per warp
// (R13/R14 structure) BUT P never touches smem: the S C-fragments are
// re-laid into PV A-fragments with warp shuffles (mapping validated R16).
// smem 70 KB -> 2 CTAs/SM with full 16-warp residency.
// Qs/Ks: pitch 72 (== 8 mod 32), k-permuted. Vs: grouped-permuted [8][64][8].
// ---------------------------------------------------------------------------
#define FP 72

__global__ __launch_bounds__(256, 2) void flash_attn_tc(const void* __restrict__ maskp)
{
    extern __shared__ unsigned smu[];
    unsigned* Qs = smu;                   // [128][FP] permuted d
    unsigned* Ks = Qs + 128 * FP;         // [64][FP]  permuted d
    unsigned* Vs = Ks + 64 * FP;          // [8][64][8] grouped-permuted

    const int b = blockIdx.z, h = blockIdx.y, qt = blockIdx.x;
    const int tid = threadIdx.x;
    const int wid = tid >> 5, lane = tid & 31;
    const int g = lane >> 2, t = lane & 3;
    const int qrow = wid * 16;
    const int src1 = (lane & 28) | (t >> 1);   // shuffle src: col t
    const int src2 = src1 + 2;                 // shuffle src: col t+4
    const bool todd = (t & 1);

    const int is_byte = g_mask_is_byte;
    const unsigned char* mask_b = (const unsigned char*)maskp;
    const int*           mask_w = (const int*)maskp;

    // Load Q tile (128 x 64), scale folded, permuted store
    #pragma unroll
    for (int e = 0; e < 8; e++) {
        int idx = tid + e * 256;
        int r = idx >> 4, d4 = (idx & 15) << 2;
        int pbq = ((d4 >> 3) << 3) | ((d4 & 4) >> 2);
        float4 qv = *(const float4*)(g_q + (size_t)(b * T_ + qt * 128 + r) * N_ + h * D_ + d4);
        unsigned* p = Qs + r * FP + pbq;
        p[0] = f2tf(qv.x * 0.125f); p[2] = f2tf(qv.y * 0.125f);
        p[4] = f2tf(qv.z * 0.125f); p[6] = f2tf(qv.w * 0.125f);
    }

    float m_i[2] = {-INFINITY, -INFINITY};
    float l_i[2] = {0.f, 0.f};
    float o[8][4];
    #pragma unroll
    for (int nt = 0; nt < 8; nt++)
        #pragma unroll
        for (int r = 0; r < 4; r++) o[nt][r] = 0.f;

    for (int kt = 0; kt < T_ / 64; kt++) {
        __syncthreads();
        // K tile (64 x 64), row-major permuted-d
        #pragma unroll
        for (int e = 0; e < 4; e++) {
            int idx = tid + e * 256;
            int r = idx >> 4, d4 = (idx & 15) << 2;
            int pbk = ((d4 >> 3) << 3) | ((d4 & 4) >> 2);
            size_t base = (size_t)(b * T_ + kt * 64 + r) * N_ + h * D_ + d4;
            float4 kv = *(const float4*)(g_k + base);
            unsigned* p = Ks + r * FP + pbk;
            p[0] = f2tf(kv.x); p[2] = f2tf(kv.y); p[4] = f2tf(kv.z); p[6] = f2tf(kv.w);
        }
        // V tile: grouped-permuted [8][64][8]
        #pragma unroll
        for (int e = 0; e < 2; e++) {
            int idx = tid + e * 256;        // 0..511
            int g8 = idx >> 6;              // k-group 0..7
            int n  = idx & 63;
            const float* vp = g_v + (size_t)(b * T_ + kt * 64 + g8 * 8) * N_ + h * D_ + n;
            unsigned vr[8];
            #pragma unroll
            for (int kr = 0; kr < 8; kr++)
                vr[pos8(kr)] = f2tf(vp[(size_t)kr * N_]);
            unsigned* vdst = Vs + g8 * 512 + n * 8;
            *(uint4*)(vdst + 0) = make_uint4(vr[0], vr[1], vr[2], vr[3]);
            *(uint4*)(vdst + 4) = make_uint4(vr[4], vr[5], vr[6], vr[7]);
        }
        __syncthreads();

        // ---- S = Q @ K^T  (warp: 16 x 64) ----
        float s[8][4];
        #pragma unroll
        for (int nt = 0; nt < 8; nt++)
            #pragma unroll
            for (int r = 0; r < 4; r++) s[nt][r] = 0.f;

        #pragma unroll
        for (int kk = 0; kk < 8; kk++) {
            uint2 qlo = *(const uint2*)(Qs + (qrow + g) * FP + kk * 8 + 2 * t);
            uint2 qhi = *(const uint2*)(Qs + (qrow + g + 8) * FP + kk * 8 + 2 * t);
            #pragma unroll
            for (int nt = 0; nt < 8; nt++) {
                uint2 kb = *(const uint2*)(Ks + (nt * 8 + g) * FP + kk * 8 + 2 * t);
                mma_tf32(s[nt], qlo.x, qhi.x, qlo.y, qhi.y, kb.x, kb.y);
            }
        }

        // ---- mask + online softmax (fp32); P stays in registers ----
        #pragma unroll
        for (int half = 0; half < 2; half++) {
            const int r0 = half * 2;
            int rowg = qt * 128 + qrow + g + half * 8;
            size_t mbase = ((size_t)b * T_ + rowg) * T_ + kt * 64;

            #pragma unroll
            for (int nt = 0; nt < 8; nt++) {
                int col = nt * 8 + 2 * t;
                int mv0, mv1;
                if (is_byte) {
                    uchar2 u = *(const uchar2*)(mask_b + mbase + col);
                    mv0 = u.x; mv1 = u.y;
                } else {
                    int2 u = *(const int2*)(mask_w + mbase + col);
                    mv0 = u.x; mv1 = u.y;
                }
                if (mv0 == 0) s[nt][r0 + 0] = -3.402823466e38f;
                if (mv1 == 0) s[nt][r0 + 1] = -3.402823466e38f;
            }

            float mx = -INFINITY;
            #pragma unroll
            for (int nt = 0; nt < 8; nt++)
                mx = fmaxf(mx, fmaxf(s[nt][r0], s[nt][r0 + 1]));
            mx = fmaxf(mx, __shfl_xor_sync(0xffffffffu, mx, 1));
            mx = fmaxf(mx, __shfl_xor_sync(0xffffffffu, mx, 2));

            float mnew = fmaxf(m_i[half], mx);
            float corr = __expf(m_i[half] - mnew);
            float rs = 0.f;
            #pragma unroll
            for (int nt = 0; nt < 8; nt++) {
                float p0 = __expf(s[nt][r0] - mnew);
                float p1 = __expf(s[nt][r0 + 1] - mnew);
                rs += p0 + p1;
                // store tf32 bits in-place (P operand for the PV mma)
                s[nt][r0]     = __uint_as_float(f2tf(p0));
                s[nt][r0 + 1] = __uint_as_float(f2tf(p1));
            }
            rs += __shfl_xor_sync(0xffffffffu, rs, 1);
            rs += __shfl_xor_sync(0xffffffffu, rs, 2);
            l_i[half] = l_i[half] * corr + rs;
            m_i[half] = mnew;
            #pragma unroll
            for (int nt = 0; nt < 8; nt++) {
                o[nt][r0] *= corr; o[nt][r0 + 1] *= corr;
            }
        }

        // ---- O += P @ V : P A-frags built by shuffle from S C-frags ----
        #pragma unroll
        for (int kk = 0; kk < 8; kk++) {
            float x0 = __shfl_sync(0xffffffffu, s[kk][0], src1);
            float x1 = __shfl_sync(0xffffffffu, s[kk][1], src1);
            float x2 = __shfl_sync(0xffffffffu, s[kk][0], src2);
            float x3 = __shfl_sync(0xffffffffu, s[kk][1], src2);
            float y0 = __shfl_sync(0xffffffffu, s[kk][2], src1);
            float y1 = __shfl_sync(0xffffffffu, s[kk][3], src1);
            float y2 = __shfl_sync(0xffffffffu, s[kk][2], src2);
            float y3 = __shfl_sync(0xffffffffu, s[kk][3], src2);
            unsigned pa0 = __float_as_uint(todd ? x1 : x0);   // P[g][t]
            unsigned pa1 = __float_as_uint(todd ? y1 : y0);   // P[g+8][t]
            unsigned pa2 = __float_as_uint(todd ? x3 : x2);   // P[g][t+4]
            unsigned pa3 = __float_as_uint(todd ? y3 : y2);   // P[g+8][t+4]
            const unsigned* vg = Vs + kk * 512;
            #pragma unroll
            for (int nt = 0; nt < 8; nt++) {
                uint2 vb = *(const uint2*)(vg + (nt * 8 + g) * 8 + 2 * t);
                mma_tf32(o[nt], pa0, pa1, pa2, pa3, vb.x, vb.y);
            }
        }
    }

    // Epilogue: normalize, write z[b,t,h,d]
    #pragma unroll
    for (int half = 0; half < 2; half++) {
        float inv = 1.f / l_i[half];
        int rowg = qt * 128 + qrow + g + half * 8;
        #pragma unroll
        for (int nt = 0; nt < 8; nt++) {
            float2 ov = make_float2(o[nt][half * 2] * inv,
                                    o[nt][half * 2 + 1] * inv);
            *(float2*)(g_z + (size_t)(b * T_ + rowg) * N_ + h * D_ + nt * 8 + 2 * t) = ov;
        }
    }
}

#define ATTN_SMEM ((128 * FP + 64 * FP + 4096) * 4)   // 71680 B = 70 KB

// ---------------------------------------------------------------------------
extern "C" void kernel_launch(void* const* d_in, const int* in_sizes, int n_in,
                              void* d_out, int out_size)
{
    const float* embed = (const float*)d_in[0];
    const void*  mask  = d_in[1];
    const float* Wq = (const float*)d_in[2]; const float* bq = (const float*)d_in[3];
    const float* Wk = (const float*)d_in[4]; const float* bk = (const float*)d_in[5];
    const float* Wv = (const float*)d_in[6]; const float* bv = (const float*)d_in[7];
    const float* Wz = (const float*)d_in[8]; const float* bz = (const float*)d_in[9];
    float* out = (float*)d_out;

    float *q, *k, *v, *z, *wt;
    cudaGetSymbolAddress((void**)&q, g_q);
    cudaGetSymbolAddress((void**)&k, g_k);
    cudaGetSymbolAddress((void**)&v, g_v);
    cudaGetSymbolAddress((void**)&z, g_z);
    cudaGetSymbolAddress((void**)&wt, g_wt);

    detect_mask_kernel<<<1, 256>>>((const unsigned int*)mask);
    transpose4<<<dim3(32, 32, 4), dim3(32, 8)>>>(Wq, Wk, Wv, Wz, wt);

    cudaFuncSetAttribute(gemm_qkv, cudaFuncAttributeMaxDynamicSharedMemorySize,
                         GEMM_SMEM);
    cudaFuncSetAttribute(gemm_one, cudaFuncAttributeMaxDynamicSharedMemorySize,
                         GEMM_SMEM);
    gemm_qkv<<<dim3(N_ / 128, M_ / 128, 3), 256, GEMM_SMEM>>>(
        embed, wt, bq, bk, bv, q, k, v);

    cudaFuncSetAttribute(flash_attn_tc,
                         cudaFuncAttributeMaxDynamicSharedMemorySize, ATTN_SMEM);
    flash_attn_tc<<<dim3(T_ / 128, H_, B_), 256, ATTN_SMEM>>>(mask);

    gemm_one<<<dim3(N_ / 128, M_ / 128), 256, GEMM_SMEM>>>(
        z, wt + 3ull * 1024 * 1024, bz, out);
}